// round 1
// baseline (speedup 1.0000x reference)
#include <cuda_runtime.h>
#include <math.h>

#define B_GRAPHS 65536
#define NPG 9
#define DIN 11
#define D 64
#define GB 8                      // graphs per block-iteration
#define NODES (GB * NPG)          // 72
#define THREADS 256
#define HSTRIDE 68                // padded row stride for h (bank-conflict-free head reads)
#define NITER (B_GRAPHS / GB)     // 8192

// biased_softplus bias: log(expm1(1.0)) = log(e - 1)
#define SOFTPLUS_BIAS 0.54132485461291809f

struct Smem {
    float WTin[12][D];      // [k][d], k=11 row zero-padded
    float WT1rel[D][D];     // [k][d]
    float WTd1[D][D];       // W1_root - W1_rel, [k][d]
    float WT2rel[D][D];
    float WTd2[D][D];
    float Wh[8][65][2];     // head weights, j-stride padded (65*2=130 floats)
    float b_in[D], b1v[D], b2v[D];
    float bh[8][2];
    float h[NODES][HSTRIDE];
    float xs[NODES][12];    // x tile, col 11 zero-padded
    float hs[GB][HSTRIDE];  // per-graph sums
    float Sg[GB][HSTRIDE];  // per-graph S = b + hs @ W_rel^T  (per dim)
};

__device__ __forceinline__ float tanh_fast(float x) {
    float y;
    asm("tanh.approx.f32 %0, %1;" : "=f"(y) : "f"(x));
    return y;
}

__device__ __forceinline__ void gnn_layer(Smem* sm, int tid, int d, int quad,
                                          const float (*WTrel)[D],
                                          const float (*WTd)[D],
                                          const float* bvec)
{
    // --- per-graph sums hs[g][k] = sum over 9 nodes of h ---
    if (tid < GB * 16) {
        int g = tid >> 4, kq = tid & 15;
        float4 s = make_float4(0.f, 0.f, 0.f, 0.f);
        #pragma unroll
        for (int n = 0; n < NPG; n++) {
            float4 v = *(const float4*)&sm->h[g * NPG + n][kq * 4];
            s.x += v.x; s.y += v.y; s.z += v.z; s.w += v.w;
        }
        *(float4*)&sm->hs[g][kq * 4] = s;
    }
    __syncthreads();

    // --- S[g][d] = b[d] + sum_k hs[g][k] * Wrel[d][k]  (each quad: 2 graphs) ---
    {
        int ga = quad * 2, gb2 = quad * 2 + 1;
        float bb = bvec[d];
        float sA = bb, sB = bb;
        #pragma unroll
        for (int kc = 0; kc < 4; kc++) {
            float w[16];
            #pragma unroll
            for (int k = 0; k < 16; k++) w[k] = WTrel[kc * 16 + k][d];
            const float4* pa = (const float4*)&sm->hs[ga][kc * 16];
            const float4* pb = (const float4*)&sm->hs[gb2][kc * 16];
            #pragma unroll
            for (int q = 0; q < 4; q++) {
                float4 va = pa[q], vb = pb[q];
                sA += va.x * w[4*q] + va.y * w[4*q+1] + va.z * w[4*q+2] + va.w * w[4*q+3];
                sB += vb.x * w[4*q] + vb.y * w[4*q+1] + vb.z * w[4*q+2] + vb.w * w[4*q+3];
            }
        }
        sm->Sg[ga][d] = sA;
        sm->Sg[gb2][d] = sB;
    }
    __syncthreads();

    // --- per-node: out = tanh(S[g] + h[n] @ (Wroot - Wrel)^T) ---
    float acc[18];
    #pragma unroll
    for (int r = 0; r < 18; r++) {
        int g = quad * 2 + (r >= 9 ? 1 : 0);
        acc[r] = sm->Sg[g][d];
    }
    #pragma unroll
    for (int kc = 0; kc < 4; kc++) {
        float w[16];
        #pragma unroll
        for (int k = 0; k < 16; k++) w[k] = WTd[kc * 16 + k][d];
        #pragma unroll
        for (int r = 0; r < 18; r++) {
            const float4* hp = (const float4*)&sm->h[quad * 18 + r][kc * 16];
            #pragma unroll
            for (int q = 0; q < 4; q++) {
                float4 v = hp[q];
                acc[r] += v.x * w[4*q] + v.y * w[4*q+1] + v.z * w[4*q+2] + v.w * w[4*q+3];
            }
        }
    }
    #pragma unroll
    for (int r = 0; r < 18; r++) acc[r] = tanh_fast(acc[r]);
    __syncthreads();   // all reads of h done before overwrite
    #pragma unroll
    for (int r = 0; r < 18; r++) sm->h[quad * 18 + r][d] = acc[r];
    __syncthreads();
}

__global__ __launch_bounds__(THREADS, 2)
void gnn_kernel(const float* __restrict__ x,
                const float* __restrict__ gW_in,  const float* __restrict__ gb_in,
                const float* __restrict__ gW1rel, const float* __restrict__ gb1,
                const float* __restrict__ gW1root,
                const float* __restrict__ gW2rel, const float* __restrict__ gb2,
                const float* __restrict__ gW2root,
                const float* __restrict__ gWhead, const float* __restrict__ gbhead,
                float* __restrict__ out)
{
    extern __shared__ char smem_raw[];
    Smem* sm = reinterpret_cast<Smem*>(smem_raw);
    const int tid = threadIdx.x;
    const int d = tid & 63;
    const int quad = tid >> 6;

    // ---- one-time weight staging (transposed) ----
    for (int i = tid; i < D * D; i += THREADS) {
        int dd = i >> 6, k = i & 63;
        float r1 = gW1rel[i];
        sm->WT1rel[k][dd] = r1;
        sm->WTd1[k][dd]  = gW1root[i] - r1;
        float r2 = gW2rel[i];
        sm->WT2rel[k][dd] = r2;
        sm->WTd2[k][dd]  = gW2root[i] - r2;
    }
    for (int i = tid; i < D * 12; i += THREADS) {
        int dd = i & 63, k = i >> 6;
        sm->WTin[k][dd] = (k < DIN) ? gW_in[dd * DIN + k] : 0.f;
    }
    for (int i = tid; i < 8 * D * 2; i += THREADS) {
        int j = i >> 7, r = i & 127, k = r >> 1, o = r & 1;
        sm->Wh[j][k][o] = gWhead[i];
    }
    if (tid < D) { sm->b_in[tid] = gb_in[tid]; sm->b1v[tid] = gb1[tid]; sm->b2v[tid] = gb2[tid]; }
    if (tid < 16) sm->bh[tid >> 1][tid & 1] = gbhead[tid];
    __syncthreads();

    for (int gb = blockIdx.x; gb < NITER; gb += gridDim.x) {
        const long long g0 = (long long)gb * GB;
        __syncthreads();  // protect h / xs from previous iteration's readers

        // ---- load x tile (72 nodes x 11, zero-padded to 12) ----
        const float* xg = x + g0 * NPG * DIN;
        for (int i = tid; i < NODES * 12; i += THREADS) {
            int n = i / 12, k = i - n * 12;
            sm->xs[n][k] = (k < DIN) ? xg[n * DIN + k] : 0.f;
        }
        __syncthreads();

        // ---- input layer: h = x @ W_in^T + b_in (no activation) ----
        {
            float win[12];
            #pragma unroll
            for (int k = 0; k < 12; k++) win[k] = sm->WTin[k][d];
            float bb = sm->b_in[d];
            #pragma unroll
            for (int r = 0; r < 18; r++) {
                int n = quad * 18 + r;
                float a = bb;
                const float4* xp = (const float4*)sm->xs[n];
                #pragma unroll
                for (int q = 0; q < 3; q++) {
                    float4 v = xp[q];
                    a += v.x * win[4*q] + v.y * win[4*q+1] + v.z * win[4*q+2] + v.w * win[4*q+3];
                }
                sm->h[n][d] = a;
            }
        }
        __syncthreads();

        gnn_layer(sm, tid, d, quad, sm->WT1rel, sm->WTd1, sm->b1v);
        gnn_layer(sm, tid, d, quad, sm->WT2rel, sm->WTd2, sm->b2v);

        // ---- heads: nodes 1..8, per-node [64 -> 2]; loc & softplus scale ----
        if (tid < GB * 8 * 2) {
            int o = tid & 1, j = (tid >> 1) & 7, g = tid >> 4;
            float a = sm->bh[j][o];
            const float4* hp = (const float4*)sm->h[g * NPG + j + 1];
            #pragma unroll
            for (int q = 0; q < 16; q++) {
                float4 v = hp[q];
                a += v.x * sm->Wh[j][4*q+0][o] + v.y * sm->Wh[j][4*q+1][o]
                   + v.z * sm->Wh[j][4*q+2][o] + v.w * sm->Wh[j][4*q+3][o];
            }
            long long gi = (g0 + g) * 8 + j;
            if (o == 0) {
                out[gi] = a;
            } else {
                float z = a + SOFTPLUS_BIAS;
                float sp = (z > 20.f) ? z : log1pf(__expf(z));
                out[(long long)B_GRAPHS * 8 + gi] = fmaxf(sp, 1e-4f);
            }
        }
    }
}

extern "C" void kernel_launch(void* const* d_in, const int* in_sizes, int n_in,
                              void* d_out, int out_size)
{
    (void)in_sizes; (void)n_in; (void)out_size;
    const float* x      = (const float*)d_in[0];
    // d_in[1] = edge_index: structurally known (dense 9-node graphs) -> unused
    const float* W_in   = (const float*)d_in[2];
    const float* b_in   = (const float*)d_in[3];
    const float* W1_rel = (const float*)d_in[4];
    const float* b1     = (const float*)d_in[5];
    const float* W1_root= (const float*)d_in[6];
    const float* W2_rel = (const float*)d_in[7];
    const float* b2     = (const float*)d_in[8];
    const float* W2_root= (const float*)d_in[9];
    const float* W_head = (const float*)d_in[10];
    const float* b_head = (const float*)d_in[11];
    float* out = (float*)d_out;

    const int smem = (int)sizeof(Smem);
    cudaFuncSetAttribute(gnn_kernel, cudaFuncAttributeMaxDynamicSharedMemorySize, smem);
    gnn_kernel<<<304, THREADS, smem>>>(x, W_in, b_in, W1_rel, b1, W1_root,
                                       W2_rel, b2, W2_root, W_head, b_head, out);
}